// round 12
// baseline (speedup 1.0000x reference)
#include <cuda_runtime.h>
#include <cuda_bf16.h>
#include <cstdint>

#define BB 16
#define CC 64
#define HH 192
#define WWID 192
#define HWSZ (HH * WWID)            // 36864
#define NSTEPS (BB * 128 * 512)     // 1,048,576 path steps
#define TPX 128                     // pixels per tile (MMA M)
#define NTILES (BB * (HWSZ / TPX))  // 4608
#define NCTAS (148 * 3)             // persistent grid (no barrier -> safe any occ)

__device__ unsigned char g_occ[BB * HWSZ];
__device__ int g_idx_is64;

// ---------------------------------------------------------------------------
__global__ void zero_probe_kernel(const int* __restrict__ words) {
    int i = blockIdx.x * blockDim.x + threadIdx.x;
    uint4* p = reinterpret_cast<uint4*>(g_occ);
    if (i < (BB * HWSZ) / 16) p[i] = make_uint4(0u, 0u, 0u, 0u);
    if (i == 0) g_idx_is64 = 1;
    if (i < 1024 && words[2 * i + 1] != 0) atomicAnd(&g_idx_is64, 0);
}

__global__ void mark_occ_kernel(const void* __restrict__ path_idx) {
    int i = blockIdx.x * blockDim.x + threadIdx.x;
    if (i < NSTEPS) {
        int b = i >> 16;
        int hw;
        if (g_idx_is64)
            hw = (int)((const long long*)path_idx)[i];
        else
            hw = ((const int*)path_idx)[i];
        if ((unsigned)hw < (unsigned)HWSZ)
            g_occ[b * HWSZ + hw] = 1;
    }
}

// ---------------------------------------------------------------------------
__device__ __forceinline__ uint32_t smem_u32(const void* p) {
    uint32_t a;
    asm("{ .reg .u64 t; cvta.to.shared.u64 t, %1; cvt.u32.u64 %0, t; }"
        : "=r"(a) : "l"(p));
    return a;
}
#define SWZ(o) ((uint32_t)(o) ^ ((((uint32_t)(o)) >> 3) & 0x70))

#define LDSM4(R, ADDR)                                                        \
    asm volatile("ldmatrix.sync.aligned.m8n8.x4.shared.b16 {%0,%1,%2,%3}, [%4];" \
                 : "=r"((R)[0]), "=r"((R)[1]), "=r"((R)[2]), "=r"((R)[3])     \
                 : "r"(ADDR))

#define MMA16816(C, A, B0, B1)                                                \
    asm volatile("mma.sync.aligned.m16n8k16.row.col.f32.bf16.bf16.f32 "       \
                 "{%0,%1,%2,%3}, {%4,%5,%6,%7}, {%8,%9}, {%0,%1,%2,%3};"      \
                 : "+f"((C)[0]), "+f"((C)[1]), "+f"((C)[2]), "+f"((C)[3])     \
                 : "r"((A)[0]), "r"((A)[1]), "r"((A)[2]), "r"((A)[3]),        \
                   "r"(B0), "r"(B1))

// ---------------------------------------------------------------------------
// Persistent masked GEMM, 256 threads/CTA, 8 warps: warp tile 32 px x 32 ch.
// Per-thread state halves vs R10 (32 accs, 32 staging LDGs) -> more warps/SM.
// k-outer MMA loop: each A/B fragment loaded once per k (8 LDSM4/k/warp).
// ---------------------------------------------------------------------------
__global__ void __launch_bounds__(256)
mma_gemm_kernel(const float* __restrict__ feat,
                const float* __restrict__ Wm,     // [64][64] (k, c)
                const float* __restrict__ bm,     // [64]
                float* __restrict__ out) {
    __shared__ __align__(1024) unsigned char sAhi[TPX * 128];  // 16 KB
    __shared__ __align__(1024) unsigned char sAlo[TPX * 128];  // 16 KB
    __shared__ __align__(1024) unsigned char sBhi[64 * 128];   // 8 KB
    __shared__ __align__(1024) unsigned char sBlo[64 * 128];   // 8 KB (48 KB)

    const int tid  = threadIdx.x;
    const int warp = tid >> 5;
    const int lane = tid & 31;

    // --- Stage B = W^T split ONCE per CTA ---
    for (int i = tid; i < 64 * 64; i += 256) {
        int n = i & 63;
        int k = i >> 6;
        float w = Wm[k * 64 + n];
        __nv_bfloat16 h = __float2bfloat16(w);
        __nv_bfloat16 l = __float2bfloat16(w - __bfloat162float(h));
        uint32_t off = SWZ((uint32_t)(n * 128 + k * 2));
        *reinterpret_cast<unsigned short*>(sBhi + off) = __bfloat16_as_ushort(h);
        *reinterpret_cast<unsigned short*>(sBlo + off) = __bfloat16_as_ushort(l);
    }

    // --- Loop-invariant addressing ---
    const int g = lane >> 2, t = lane & 3;
    const int wpx = (warp & 3) * 32;        // warp's pixel base within tile
    const int wch = (warp >> 2) * 32;       // warp's channel base
    const uint32_t mask   = (uint32_t)(lane & 7) << 4;
    const uint32_t aRowA  = (uint32_t)(wpx + (lane & 15)) * 128;
    const uint32_t aChunk = (uint32_t)(lane & 16);
    const uint32_t bRowA  = (uint32_t)(wch + (lane & 7) + ((lane & 16) >> 1)) * 128;
    const uint32_t bChunk = (uint32_t)((lane & 8) << 1);
    const uint32_t aHi = smem_u32(sAhi);
    const uint32_t aLo = smem_u32(sAlo);
    const uint32_t bHiA = smem_u32(sBhi);
    const uint32_t bLoA = smem_u32(sBlo);

    float bias0[4], bias1[4];
    #pragma unroll
    for (int n = 0; n < 4; n++) {
        bias0[n] = __ldg(&bm[wch + n * 8 + 2 * t]);
        bias1[n] = __ldg(&bm[wch + n * 8 + 2 * t + 1]);
    }

    // Staging role: thread = (pixel p, k-half)
    const int sp    = tid & 127;             // pixel within tile
    const int khalf = tid >> 7;              // 0: k 0..31, 1: k 32..63
    const uint32_t sArow = (uint32_t)sp * 128 + (uint32_t)khalf * 64;

    // --- Persistent tile loop ---
    for (int tile = blockIdx.x; tile < NTILES; tile += NCTAS) {
        const int b   = tile / (HWSZ / TPX);
        const int hw0 = (tile - b * (HWSZ / TPX)) * TPX;

        // Stage A: 32 batched strided LDGs per thread, convert, STS.128
        {
            const float* fbase = feat + (size_t)b * CC * HWSZ + hw0 + sp;
            #pragma unroll
            for (int c = 0; c < 4; c++) {         // 4 chunks x 8 k (16 B)
                uint32_t hp[4], lp[4];
                #pragma unroll
                for (int j = 0; j < 4; j++) {
                    int k0 = khalf * 32 + c * 8 + 2 * j;
                    float a0 = fbase[(size_t)k0 * HWSZ];
                    float a1 = fbase[(size_t)(k0 + 1) * HWSZ];
                    __nv_bfloat16 h0 = __float2bfloat16(a0);
                    __nv_bfloat16 h1 = __float2bfloat16(a1);
                    __nv_bfloat16 l0 = __float2bfloat16(a0 - __bfloat162float(h0));
                    __nv_bfloat16 l1 = __float2bfloat16(a1 - __bfloat162float(h1));
                    hp[j] = (uint32_t)__bfloat16_as_ushort(h0) |
                            ((uint32_t)__bfloat16_as_ushort(h1) << 16);
                    lp[j] = (uint32_t)__bfloat16_as_ushort(l0) |
                            ((uint32_t)__bfloat16_as_ushort(l1) << 16);
                }
                uint32_t off = SWZ(sArow + c * 16);
                asm volatile("st.shared.v4.b32 [%0], {%1, %2, %3, %4};"
                             :: "r"(aHi + off),
                                "r"(hp[0]), "r"(hp[1]), "r"(hp[2]), "r"(hp[3]) : "memory");
                asm volatile("st.shared.v4.b32 [%0], {%1, %2, %3, %4};"
                             :: "r"(aLo + off),
                                "r"(lp[0]), "r"(lp[1]), "r"(lp[2]), "r"(lp[3]) : "memory");
            }
        }
        __syncthreads();

        // MMA: k-outer; load each fragment once per k; 3 split-products fused
        float c_[2][4][4];
        #pragma unroll
        for (int m = 0; m < 2; m++)
            #pragma unroll
            for (int n = 0; n < 4; n++)
                #pragma unroll
                for (int r = 0; r < 4; r++) c_[m][n][r] = 0.0f;

        #pragma unroll
        for (int k = 0; k < 4; k++) {
            const uint32_t ac = (aChunk + (uint32_t)k * 32) ^ mask;  // no carry
            const uint32_t bc = (bChunk + (uint32_t)k * 32) ^ mask;
            uint32_t ah0[4], ah1[4], al0[4], al1[4];
            LDSM4(ah0, aHi + aRowA + ac);
            LDSM4(ah1, aHi + aRowA + 2048 + ac);
            LDSM4(al0, aLo + aRowA + ac);
            LDSM4(al1, aLo + aRowA + 2048 + ac);
            uint32_t bh[4][2], bl[4][2];
            #pragma unroll
            for (int np2 = 0; np2 < 2; np2++) {
                uint32_t r4[4];
                LDSM4(r4, bHiA + bRowA + (uint32_t)np2 * 2048 + bc);
                bh[2 * np2][0] = r4[0]; bh[2 * np2][1] = r4[1];
                bh[2 * np2 + 1][0] = r4[2]; bh[2 * np2 + 1][1] = r4[3];
                LDSM4(r4, bLoA + bRowA + (uint32_t)np2 * 2048 + bc);
                bl[2 * np2][0] = r4[0]; bl[2 * np2][1] = r4[1];
                bl[2 * np2 + 1][0] = r4[2]; bl[2 * np2 + 1][1] = r4[3];
            }
            #pragma unroll
            for (int n = 0; n < 4; n++) {
                MMA16816(c_[0][n], ah0, bh[n][0], bh[n][1]);   // hi*hi
                MMA16816(c_[1][n], ah1, bh[n][0], bh[n][1]);
                MMA16816(c_[0][n], ah0, bl[n][0], bl[n][1]);   // hi*lo
                MMA16816(c_[1][n], ah1, bl[n][0], bl[n][1]);
                MMA16816(c_[0][n], al0, bh[n][0], bh[n][1]);   // lo*hi
                MMA16816(c_[1][n], al1, bh[n][0], bh[n][1]);
            }
        }

        // Epilogue: mask + bias; stores are full 32B sectors per channel row
        const unsigned char* occp = g_occ + b * HWSZ + hw0 + wpx + g;
        float msk[4];
        msk[0] = occp[0]  ? 1.0f : 0.0f;
        msk[1] = occp[8]  ? 1.0f : 0.0f;
        msk[2] = occp[16] ? 1.0f : 0.0f;
        msk[3] = occp[24] ? 1.0f : 0.0f;

        float* ob = out + (size_t)b * CC * HWSZ;
        #pragma unroll
        for (int m = 0; m < 2; m++) {
            const int hwA = hw0 + wpx + m * 16 + g;
            const int hwB = hwA + 8;
            const float mA = msk[2 * m], mB = msk[2 * m + 1];
            #pragma unroll
            for (int n = 0; n < 4; n++) {
                const size_t ch = (size_t)(wch + n * 8 + 2 * t);
                ob[ch * HWSZ + hwA]       = (c_[m][n][0] + bias0[n]) * mA;
                ob[(ch + 1) * HWSZ + hwA] = (c_[m][n][1] + bias1[n]) * mA;
                ob[ch * HWSZ + hwB]       = (c_[m][n][2] + bias0[n]) * mB;
                ob[(ch + 1) * HWSZ + hwB] = (c_[m][n][3] + bias1[n]) * mB;
            }
        }
        __syncthreads();   // all warps done reading sA before next staging
    }
}

// ---------------------------------------------------------------------------
extern "C" void kernel_launch(void* const* d_in, const int* in_sizes, int n_in,
                              void* d_out, int out_size) {
    const float* feat = (const float*)d_in[0];      // [B, C, H, W] f32
    const void*  pidx = d_in[1];                    // [B, P, L] int32 or int64
    const float* Wm   = (const float*)d_in[2];      // [C, C] f32
    const float* bm   = (const float*)d_in[3];      // [C] f32
    float*       out  = (float*)d_out;              // [B, C, H, W] f32

    (void)in_sizes; (void)n_in; (void)out_size;

    zero_probe_kernel<<<(BB * HWSZ / 16 + 255) / 256, 256>>>((const int*)pidx);
    mark_occ_kernel<<<(NSTEPS + 255) / 256, 256>>>(pidx);

    mma_gemm_kernel<<<NCTAS, 256>>>(feat, Wm, bm, out);
}

// round 13
// speedup vs baseline: 1.0181x; 1.0181x over previous
#include <cuda_runtime.h>
#include <cuda_bf16.h>
#include <cstdint>

#define BB 16
#define CC 64
#define HH 192
#define WWID 192
#define HWSZ (HH * WWID)            // 36864
#define NSTEPS (BB * 128 * 512)     // 1,048,576 path steps
#define TPX 128                     // pixels per tile (MMA M)
#define NTILES (BB * (HWSZ / TPX))  // 4608
#define NCTAS (148 * 3)             // persistent grid

__device__ unsigned char g_occ[BB * HWSZ];
__device__ int g_idx_is64;

// ---------------------------------------------------------------------------
__global__ void zero_probe_kernel(const int* __restrict__ words) {
    int i = blockIdx.x * blockDim.x + threadIdx.x;
    uint4* p = reinterpret_cast<uint4*>(g_occ);
    if (i < (BB * HWSZ) / 16) p[i] = make_uint4(0u, 0u, 0u, 0u);
    if (i == 0) g_idx_is64 = 1;
    if (i < 1024 && words[2 * i + 1] != 0) atomicAnd(&g_idx_is64, 0);
}

__global__ void mark_occ_kernel(const void* __restrict__ path_idx) {
    int i = blockIdx.x * blockDim.x + threadIdx.x;
    if (i < NSTEPS) {
        int b = i >> 16;
        int hw;
        if (g_idx_is64)
            hw = (int)((const long long*)path_idx)[i];
        else
            hw = ((const int*)path_idx)[i];
        if ((unsigned)hw < (unsigned)HWSZ)
            g_occ[b * HWSZ + hw] = 1;
    }
}

// ---------------------------------------------------------------------------
__device__ __forceinline__ uint32_t smem_u32(const void* p) {
    uint32_t a;
    asm("{ .reg .u64 t; cvta.to.shared.u64 t, %1; cvt.u32.u64 %0, t; }"
        : "=r"(a) : "l"(p));
    return a;
}
#define SWZ(o) ((uint32_t)(o) ^ ((((uint32_t)(o)) >> 3) & 0x70))

#define LDSM4(R, ADDR)                                                        \
    asm volatile("ldmatrix.sync.aligned.m8n8.x4.shared.b16 {%0,%1,%2,%3}, [%4];" \
                 : "=r"((R)[0]), "=r"((R)[1]), "=r"((R)[2]), "=r"((R)[3])     \
                 : "r"(ADDR))

#define MMA16816(C, A, B0, B1)                                                \
    asm volatile("mma.sync.aligned.m16n8k16.row.col.f32.bf16.bf16.f32 "       \
                 "{%0,%1,%2,%3}, {%4,%5,%6,%7}, {%8,%9}, {%0,%1,%2,%3};"      \
                 : "+f"((C)[0]), "+f"((C)[1]), "+f"((C)[2]), "+f"((C)[3])     \
                 : "r"((A)[0]), "r"((A)[1]), "r"((A)[2]), "r"((A)[3]),        \
                   "r"(B0), "r"(B1))

// ---------------------------------------------------------------------------
// Persistent masked GEMM with cross-tile register pipelining:
//   loop: convert v -> sA (tile i) ; sync ; LDG-batch tile i+1 -> v ;
//         MMA tile i ; epilogue tile i ; sync
// The 64-deep LDG burst (the proven-fast staging shape) drains behind the
// 96 HMMA + epilogue of the previous tile instead of stalling.
// ---------------------------------------------------------------------------
__global__ void __launch_bounds__(128)
mma_gemm_kernel(const float* __restrict__ feat,
                const float* __restrict__ Wm,     // [64][64] (k, c)
                const float* __restrict__ bm,     // [64]
                float* __restrict__ out) {
    __shared__ __align__(1024) unsigned char sAhi[TPX * 128];  // 16 KB
    __shared__ __align__(1024) unsigned char sAlo[TPX * 128];  // 16 KB
    __shared__ __align__(1024) unsigned char sBhi[64 * 128];   // 8 KB
    __shared__ __align__(1024) unsigned char sBlo[64 * 128];   // 8 KB (48 KB)

    const int tid  = threadIdx.x;
    const int warp = tid >> 5;
    const int lane = tid & 31;

    // --- Stage B = W^T split ONCE per CTA ---
    for (int i = tid; i < 64 * 64; i += 128) {
        int n = i & 63;
        int k = i >> 6;
        float w = Wm[k * 64 + n];
        __nv_bfloat16 h = __float2bfloat16(w);
        __nv_bfloat16 l = __float2bfloat16(w - __bfloat162float(h));
        uint32_t off = SWZ((uint32_t)(n * 128 + k * 2));
        *reinterpret_cast<unsigned short*>(sBhi + off) = __bfloat16_as_ushort(h);
        *reinterpret_cast<unsigned short*>(sBlo + off) = __bfloat16_as_ushort(l);
    }

    // --- Loop-invariant addressing ---
    const int g = lane >> 2, t = lane & 3;
    const int px = warp * 32;
    const uint32_t mask   = (uint32_t)(lane & 7) << 4;
    const uint32_t aRow   = (uint32_t)(px + (lane & 15)) * 128;
    const uint32_t aChunk = (uint32_t)(lane & 16);
    const uint32_t bRow   = (uint32_t)((lane & 7) + ((lane & 16) >> 1)) * 128;
    const uint32_t bChunk = (uint32_t)((lane & 8) << 1);
    const uint32_t aHi = smem_u32(sAhi);
    const uint32_t aLo = smem_u32(sAlo);
    const uint32_t aBases[3] = { aHi, aHi, aLo };
    const uint32_t bBases[3] = { smem_u32(sBhi), smem_u32(sBlo), smem_u32(sBhi) };
    const uint32_t arow = (uint32_t)tid * 128;

    // --- Prologue: LDG-batch tile 0 into registers ---
    float v[64];
    {
        const int tile0 = blockIdx.x;
        const int b0    = tile0 / (HWSZ / TPX);
        const int hw0   = (tile0 - b0 * (HWSZ / TPX)) * TPX;
        const float* fbase = feat + (size_t)b0 * CC * HWSZ + hw0 + tid;
        #pragma unroll
        for (int k = 0; k < 64; k++) v[k] = fbase[(size_t)k * HWSZ];
    }

    // --- Persistent pipelined tile loop ---
    for (int tile = blockIdx.x; tile < NTILES; tile += NCTAS) {
        const int b   = tile / (HWSZ / TPX);
        const int hw0 = (tile - b * (HWSZ / TPX)) * TPX;

        // Convert tile i's registers -> bf16 hi/lo split in sA
        #pragma unroll
        for (int c = 0; c < 8; c++) {
            uint32_t hp[4], lp[4];
            #pragma unroll
            for (int j = 0; j < 4; j++) {
                float a0 = v[c * 8 + 2 * j];
                float a1 = v[c * 8 + 2 * j + 1];
                __nv_bfloat16 h0 = __float2bfloat16(a0);
                __nv_bfloat16 h1 = __float2bfloat16(a1);
                __nv_bfloat16 l0 = __float2bfloat16(a0 - __bfloat162float(h0));
                __nv_bfloat16 l1 = __float2bfloat16(a1 - __bfloat162float(h1));
                hp[j] = (uint32_t)__bfloat16_as_ushort(h0) |
                        ((uint32_t)__bfloat16_as_ushort(h1) << 16);
                lp[j] = (uint32_t)__bfloat16_as_ushort(l0) |
                        ((uint32_t)__bfloat16_as_ushort(l1) << 16);
            }
            uint32_t off = SWZ(arow + c * 16);
            asm volatile("st.shared.v4.b32 [%0], {%1, %2, %3, %4};"
                         :: "r"(aHi + off),
                            "r"(hp[0]), "r"(hp[1]), "r"(hp[2]), "r"(hp[3]) : "memory");
            asm volatile("st.shared.v4.b32 [%0], {%1, %2, %3, %4};"
                         :: "r"(aLo + off),
                            "r"(lp[0]), "r"(lp[1]), "r"(lp[2]), "r"(lp[3]) : "memory");
        }
        __syncthreads();

        // Issue tile i+1's LDG burst NOW; it drains behind the MMA below.
        const int nxt = tile + NCTAS;
        if (nxt < NTILES) {
            const int bn   = nxt / (HWSZ / TPX);
            const int hwn  = (nxt - bn * (HWSZ / TPX)) * TPX;
            const float* fn = feat + (size_t)bn * CC * HWSZ + hwn + tid;
            #pragma unroll
            for (int k = 0; k < 64; k++) v[k] = fn[(size_t)k * HWSZ];
        }

        // MMA: 3 split passes x 4 K-steps (tile i, from sA/sB)
        float c_[2][8][4];
        #pragma unroll
        for (int m = 0; m < 2; m++)
            #pragma unroll
            for (int n = 0; n < 8; n++)
                #pragma unroll
                for (int r = 0; r < 4; r++) c_[m][n][r] = 0.0f;

        #pragma unroll
        for (int ps = 0; ps < 3; ps++) {
            const uint32_t aB = aBases[ps] + aRow;
            const uint32_t bB = bBases[ps] + bRow;
            #pragma unroll
            for (int k = 0; k < 4; k++) {
                const uint32_t ac = (aChunk + (uint32_t)k * 32) ^ mask;  // no carry
                const uint32_t bc = (bChunk + (uint32_t)k * 32) ^ mask;
                uint32_t a0[4], a1[4];
                LDSM4(a0, aB + ac);
                LDSM4(a1, aB + 2048 + ac);
                uint32_t bf[8][2];
                #pragma unroll
                for (int np = 0; np < 4; np++) {
                    uint32_t r4[4];
                    LDSM4(r4, bB + (uint32_t)np * 2048 + bc);
                    bf[2 * np][0] = r4[0]; bf[2 * np][1] = r4[1];
                    bf[2 * np + 1][0] = r4[2]; bf[2 * np + 1][1] = r4[3];
                }
                #pragma unroll
                for (int n = 0; n < 8; n++) {
                    MMA16816(c_[0][n], a0, bf[n][0], bf[n][1]);
                    MMA16816(c_[1][n], a1, bf[n][0], bf[n][1]);
                }
            }
        }

        // Epilogue: mask + bias (bias reloaded per tile: L1-resident)
        const unsigned char* occp = g_occ + b * HWSZ + hw0 + px + g;
        float msk[4];
        msk[0] = occp[0]  ? 1.0f : 0.0f;
        msk[1] = occp[8]  ? 1.0f : 0.0f;
        msk[2] = occp[16] ? 1.0f : 0.0f;
        msk[3] = occp[24] ? 1.0f : 0.0f;

        float* ob = out + (size_t)b * CC * HWSZ;
        #pragma unroll
        for (int m = 0; m < 2; m++) {
            const int hwA = hw0 + px + m * 16 + g;
            const int hwB = hwA + 8;
            const float mA = msk[2 * m], mB = msk[2 * m + 1];
            #pragma unroll
            for (int n = 0; n < 8; n++) {
                const size_t ch = (size_t)(n * 8 + 2 * t);
                const float b0 = __ldg(&bm[ch]);
                const float b1 = __ldg(&bm[ch + 1]);
                ob[ch * HWSZ + hwA]       = (c_[m][n][0] + b0) * mA;
                ob[(ch + 1) * HWSZ + hwA] = (c_[m][n][1] + b1) * mA;
                ob[ch * HWSZ + hwB]       = (c_[m][n][2] + b0) * mB;
                ob[(ch + 1) * HWSZ + hwB] = (c_[m][n][3] + b1) * mB;
            }
        }
        __syncthreads();   // all warps done reading sA before next convert
    }
}

// ---------------------------------------------------------------------------
extern "C" void kernel_launch(void* const* d_in, const int* in_sizes, int n_in,
                              void* d_out, int out_size) {
    const float* feat = (const float*)d_in[0];      // [B, C, H, W] f32
    const void*  pidx = d_in[1];                    // [B, P, L] int32 or int64
    const float* Wm   = (const float*)d_in[2];      // [C, C] f32
    const float* bm   = (const float*)d_in[3];      // [C] f32
    float*       out  = (float*)d_out;              // [B, C, H, W] f32

    (void)in_sizes; (void)n_in; (void)out_size;

    zero_probe_kernel<<<(BB * HWSZ / 16 + 255) / 256, 256>>>((const int*)pidx);
    mark_occ_kernel<<<(NSTEPS + 255) / 256, 256>>>(pidx);

    mma_gemm_kernel<<<NCTAS, 128>>>(feat, Wm, bm, out);
}

// round 14
// speedup vs baseline: 1.2359x; 1.2140x over previous
#include <cuda_runtime.h>
#include <cuda_bf16.h>
#include <cstdint>

#define BB 16
#define CC 64
#define HH 192
#define WWID 192
#define HWSZ (HH * WWID)            // 36864
#define NSTEPS (BB * 128 * 512)     // 1,048,576 path steps
#define TPX 128                     // pixels per tile (MMA M)
#define NTILES (BB * (HWSZ / TPX))  // 4608
#define NCTAS (148 * 3)             // persistent grid

__device__ unsigned char g_occ[BB * HWSZ];
__device__ int g_idx_is64;

// ---------------------------------------------------------------------------
__global__ void zero_probe_kernel(const int* __restrict__ words) {
    int i = blockIdx.x * blockDim.x + threadIdx.x;
    uint4* p = reinterpret_cast<uint4*>(g_occ);
    if (i < (BB * HWSZ) / 16) p[i] = make_uint4(0u, 0u, 0u, 0u);
    if (i == 0) g_idx_is64 = 1;
    if (i < 1024 && words[2 * i + 1] != 0) atomicAnd(&g_idx_is64, 0);
}

__global__ void mark_occ_kernel(const void* __restrict__ path_idx) {
    int i = blockIdx.x * blockDim.x + threadIdx.x;
    if (i < NSTEPS) {
        int b = i >> 16;
        int hw;
        if (g_idx_is64)
            hw = (int)((const long long*)path_idx)[i];
        else
            hw = ((const int*)path_idx)[i];
        if ((unsigned)hw < (unsigned)HWSZ)
            g_occ[b * HWSZ + hw] = 1;
    }
}

// ---------------------------------------------------------------------------
__device__ __forceinline__ uint32_t smem_u32(const void* p) {
    uint32_t a;
    asm("{ .reg .u64 t; cvta.to.shared.u64 t, %1; cvt.u32.u64 %0, t; }"
        : "=r"(a) : "l"(p));
    return a;
}
#define SWZ(o) ((uint32_t)(o) ^ ((((uint32_t)(o)) >> 3) & 0x70))

#define LDSM4(R, ADDR)                                                        \
    asm volatile("ldmatrix.sync.aligned.m8n8.x4.shared.b16 {%0,%1,%2,%3}, [%4];" \
                 : "=r"((R)[0]), "=r"((R)[1]), "=r"((R)[2]), "=r"((R)[3])     \
                 : "r"(ADDR))

#define MMA16816(C, A, B0, B1)                                                \
    asm volatile("mma.sync.aligned.m16n8k16.row.col.f32.bf16.bf16.f32 "       \
                 "{%0,%1,%2,%3}, {%4,%5,%6,%7}, {%8,%9}, {%0,%1,%2,%3};"      \
                 : "+f"((C)[0]), "+f"((C)[1]), "+f"((C)[2]), "+f"((C)[3])     \
                 : "r"((A)[0]), "r"((A)[1]), "r"((A)[2]), "r"((A)[3]),        \
                   "r"(B0), "r"(B1))

// ---------------------------------------------------------------------------
// Persistent masked GEMM (R10 champion shape). ONLY change: MMA loop is
// k-outer so each k's A/B fragments are loaded ONCE (48 LDSM4/tile/warp vs
// 72) and bHi is reused for the hi*hi and lo*hi split passes.
// ---------------------------------------------------------------------------
__global__ void __launch_bounds__(128, 3)
mma_gemm_kernel(const float* __restrict__ feat,
                const float* __restrict__ Wm,     // [64][64] (k, c)
                const float* __restrict__ bm,     // [64]
                float* __restrict__ out) {
    __shared__ __align__(1024) unsigned char sAhi[TPX * 128];  // 16 KB
    __shared__ __align__(1024) unsigned char sAlo[TPX * 128];  // 16 KB
    __shared__ __align__(1024) unsigned char sBhi[64 * 128];   // 8 KB
    __shared__ __align__(1024) unsigned char sBlo[64 * 128];   // 8 KB (48 KB)

    const int tid  = threadIdx.x;
    const int warp = tid >> 5;
    const int lane = tid & 31;

    // --- Stage B = W^T split ONCE per CTA ---
    for (int i = tid; i < 64 * 64; i += 128) {
        int n = i & 63;
        int k = i >> 6;
        float w = Wm[k * 64 + n];
        __nv_bfloat16 h = __float2bfloat16(w);
        __nv_bfloat16 l = __float2bfloat16(w - __bfloat162float(h));
        uint32_t off = SWZ((uint32_t)(n * 128 + k * 2));
        *reinterpret_cast<unsigned short*>(sBhi + off) = __bfloat16_as_ushort(h);
        *reinterpret_cast<unsigned short*>(sBlo + off) = __bfloat16_as_ushort(l);
    }

    // --- Loop-invariant addressing ---
    const int g = lane >> 2, t = lane & 3;
    const int px = warp * 32;
    const uint32_t mask   = (uint32_t)(lane & 7) << 4;
    const uint32_t aRow   = (uint32_t)(px + (lane & 15)) * 128;
    const uint32_t aChunk = (uint32_t)(lane & 16);
    const uint32_t bRow   = (uint32_t)((lane & 7) + ((lane & 16) >> 1)) * 128;
    const uint32_t bChunk = (uint32_t)((lane & 8) << 1);
    const uint32_t aHi = smem_u32(sAhi);
    const uint32_t aLo = smem_u32(sAlo);
    const uint32_t bHiA = smem_u32(sBhi);
    const uint32_t bLoA = smem_u32(sBlo);

    float bias0[8], bias1[8];
    #pragma unroll
    for (int n = 0; n < 8; n++) {
        bias0[n] = __ldg(&bm[n * 8 + 2 * t]);
        bias1[n] = __ldg(&bm[n * 8 + 2 * t + 1]);
    }

    // --- Persistent tile loop ---
    for (int tile = blockIdx.x; tile < NTILES; tile += NCTAS) {
        const int b   = tile / (HWSZ / TPX);
        const int hw0 = (tile - b * (HWSZ / TPX)) * TPX;

        // Stage A: thread = pixel; 64 batched strided LDGs, convert, STS.128
        {
            const float* fbase = feat + (size_t)b * CC * HWSZ + hw0 + tid;
            const uint32_t arow = (uint32_t)tid * 128;
            #pragma unroll
            for (int c = 0; c < 8; c++) {
                uint32_t hp[4], lp[4];
                #pragma unroll
                for (int j = 0; j < 4; j++) {
                    int k0 = c * 8 + 2 * j;
                    float a0 = fbase[(size_t)k0 * HWSZ];
                    float a1 = fbase[(size_t)(k0 + 1) * HWSZ];
                    __nv_bfloat16 h0 = __float2bfloat16(a0);
                    __nv_bfloat16 h1 = __float2bfloat16(a1);
                    __nv_bfloat16 l0 = __float2bfloat16(a0 - __bfloat162float(h0));
                    __nv_bfloat16 l1 = __float2bfloat16(a1 - __bfloat162float(h1));
                    hp[j] = (uint32_t)__bfloat16_as_ushort(h0) |
                            ((uint32_t)__bfloat16_as_ushort(h1) << 16);
                    lp[j] = (uint32_t)__bfloat16_as_ushort(l0) |
                            ((uint32_t)__bfloat16_as_ushort(l1) << 16);
                }
                uint32_t off = SWZ(arow + c * 16);
                asm volatile("st.shared.v4.b32 [%0], {%1, %2, %3, %4};"
                             :: "r"(aHi + off),
                                "r"(hp[0]), "r"(hp[1]), "r"(hp[2]), "r"(hp[3]) : "memory");
                asm volatile("st.shared.v4.b32 [%0], {%1, %2, %3, %4};"
                             :: "r"(aLo + off),
                                "r"(lp[0]), "r"(lp[1]), "r"(lp[2]), "r"(lp[3]) : "memory");
            }
        }
        __syncthreads();

        // MMA: k-outer; each k's fragments loaded once; bHi reused twice
        float c_[2][8][4];
        #pragma unroll
        for (int m = 0; m < 2; m++)
            #pragma unroll
            for (int n = 0; n < 8; n++)
                #pragma unroll
                for (int r = 0; r < 4; r++) c_[m][n][r] = 0.0f;

        #pragma unroll
        for (int k = 0; k < 4; k++) {
            const uint32_t ac = (aChunk + (uint32_t)k * 32) ^ mask;  // no carry
            const uint32_t bc = (bChunk + (uint32_t)k * 32) ^ mask;
            uint32_t ah0[4], ah1[4], al0[4], al1[4];
            LDSM4(ah0, aHi + aRow + ac);
            LDSM4(ah1, aHi + aRow + 2048 + ac);
            LDSM4(al0, aLo + aRow + ac);
            LDSM4(al1, aLo + aRow + 2048 + ac);
            uint32_t bh[8][2], bl[8][2];
            #pragma unroll
            for (int np = 0; np < 4; np++) {
                uint32_t r4[4];
                LDSM4(r4, bHiA + bRow + (uint32_t)np * 2048 + bc);
                bh[2 * np][0] = r4[0]; bh[2 * np][1] = r4[1];
                bh[2 * np + 1][0] = r4[2]; bh[2 * np + 1][1] = r4[3];
                LDSM4(r4, bLoA + bRow + (uint32_t)np * 2048 + bc);
                bl[2 * np][0] = r4[0]; bl[2 * np][1] = r4[1];
                bl[2 * np + 1][0] = r4[2]; bl[2 * np + 1][1] = r4[3];
            }
            #pragma unroll
            for (int n = 0; n < 8; n++) {
                MMA16816(c_[0][n], ah0, bh[n][0], bh[n][1]);   // hi*hi
                MMA16816(c_[1][n], ah1, bh[n][0], bh[n][1]);
                MMA16816(c_[0][n], ah0, bl[n][0], bl[n][1]);   // hi*lo
                MMA16816(c_[1][n], ah1, bl[n][0], bl[n][1]);
                MMA16816(c_[0][n], al0, bh[n][0], bh[n][1]);   // lo*hi
                MMA16816(c_[1][n], al1, bh[n][0], bh[n][1]);
            }
        }

        // Epilogue: mask + bias; per-channel stores are full 32B sectors
        const unsigned char* occp = g_occ + b * HWSZ + hw0 + px + g;
        float msk[4];
        msk[0] = occp[0]  ? 1.0f : 0.0f;
        msk[1] = occp[8]  ? 1.0f : 0.0f;
        msk[2] = occp[16] ? 1.0f : 0.0f;
        msk[3] = occp[24] ? 1.0f : 0.0f;

        float* ob = out + (size_t)b * CC * HWSZ;
        #pragma unroll
        for (int m = 0; m < 2; m++) {
            const int hwA = hw0 + px + m * 16 + g;
            const int hwB = hwA + 8;
            const float mA = msk[2 * m], mB = msk[2 * m + 1];
            #pragma unroll
            for (int n = 0; n < 8; n++) {
                const size_t ch = (size_t)(n * 8 + 2 * t);
                ob[ch * HWSZ + hwA]       = (c_[m][n][0] + bias0[n]) * mA;
                ob[(ch + 1) * HWSZ + hwA] = (c_[m][n][1] + bias1[n]) * mA;
                ob[ch * HWSZ + hwB]       = (c_[m][n][2] + bias0[n]) * mB;
                ob[(ch + 1) * HWSZ + hwB] = (c_[m][n][3] + bias1[n]) * mB;
            }
        }
        __syncthreads();   // all warps done reading sA before next staging
    }
}

// ---------------------------------------------------------------------------
extern "C" void kernel_launch(void* const* d_in, const int* in_sizes, int n_in,
                              void* d_out, int out_size) {
    const float* feat = (const float*)d_in[0];      // [B, C, H, W] f32
    const void*  pidx = d_in[1];                    // [B, P, L] int32 or int64
    const float* Wm   = (const float*)d_in[2];      // [C, C] f32
    const float* bm   = (const float*)d_in[3];      // [C] f32
    float*       out  = (float*)d_out;              // [B, C, H, W] f32

    (void)in_sizes; (void)n_in; (void)out_size;

    zero_probe_kernel<<<(BB * HWSZ / 16 + 255) / 256, 256>>>((const int*)pidx);
    mark_occ_kernel<<<(NSTEPS + 255) / 256, 256>>>(pidx);

    mma_gemm_kernel<<<NCTAS, 128>>>(feat, Wm, bm, out);
}

// round 15
// speedup vs baseline: 1.3439x; 1.0874x over previous
#include <cuda_runtime.h>
#include <cuda_bf16.h>
#include <cstdint>

#define BB 16
#define CC 64
#define HH 192
#define WWID 192
#define HWSZ (HH * WWID)            // 36864
#define NSTEPS (BB * 128 * 512)     // 1,048,576 path steps
#define TPX 128                     // pixels per tile (MMA M)
#define NTILES (BB * (HWSZ / TPX))  // 4608
#define NCTAS (148 * 3)             // persistent grid

__device__ unsigned char g_occ[BB * HWSZ];
__device__ int g_idx_is64;

// ---------------------------------------------------------------------------
__global__ void zero_probe_kernel(const int* __restrict__ words) {
    int i = blockIdx.x * blockDim.x + threadIdx.x;
    uint4* p = reinterpret_cast<uint4*>(g_occ);
    if (i < (BB * HWSZ) / 16) p[i] = make_uint4(0u, 0u, 0u, 0u);
    if (i == 0) g_idx_is64 = 1;
    if (i < 1024 && words[2 * i + 1] != 0) atomicAnd(&g_idx_is64, 0);
}

__global__ void mark_occ_kernel(const void* __restrict__ path_idx) {
    int i = blockIdx.x * blockDim.x + threadIdx.x;
    if (i < NSTEPS) {
        int b = i >> 16;
        int hw;
        if (g_idx_is64)
            hw = (int)((const long long*)path_idx)[i];
        else
            hw = ((const int*)path_idx)[i];
        if ((unsigned)hw < (unsigned)HWSZ)
            g_occ[b * HWSZ + hw] = 1;
    }
}

// ---------------------------------------------------------------------------
__device__ __forceinline__ uint32_t smem_u32(const void* p) {
    uint32_t a;
    asm("{ .reg .u64 t; cvta.to.shared.u64 t, %1; cvt.u32.u64 %0, t; }"
        : "=r"(a) : "l"(p));
    return a;
}
#define SWZ(o) ((uint32_t)(o) ^ ((((uint32_t)(o)) >> 3) & 0x70))

#define LDSM4(R, ADDR)                                                        \
    asm volatile("ldmatrix.sync.aligned.m8n8.x4.shared.b16 {%0,%1,%2,%3}, [%4];" \
                 : "=r"((R)[0]), "=r"((R)[1]), "=r"((R)[2]), "=r"((R)[3])     \
                 : "r"(ADDR))

#define MMA16816(C, A, B0, B1)                                                \
    asm volatile("mma.sync.aligned.m16n8k16.row.col.f32.bf16.bf16.f32 "       \
                 "{%0,%1,%2,%3}, {%4,%5,%6,%7}, {%8,%9}, {%0,%1,%2,%3};"      \
                 : "+f"((C)[0]), "+f"((C)[1]), "+f"((C)[2]), "+f"((C)[3])     \
                 : "r"((A)[0]), "r"((A)[1]), "r"((A)[2]), "r"((A)[3]),        \
                   "r"(B0), "r"(B1))

#define PREFETCH_L2(ADDR)                                                     \
    asm volatile("prefetch.global.L2 [%0];" :: "l"(ADDR))

// ---------------------------------------------------------------------------
// Persistent masked GEMM (R14 champion). ONLY change: after staging tile i,
// issue register-free prefetch.global.L2 for tile i+1's 64 lines so its
// staging burst hits L2 (~250cy) instead of DRAM (~600cy).
// ---------------------------------------------------------------------------
__global__ void __launch_bounds__(128, 3)
mma_gemm_kernel(const float* __restrict__ feat,
                const float* __restrict__ Wm,     // [64][64] (k, c)
                const float* __restrict__ bm,     // [64]
                float* __restrict__ out) {
    __shared__ __align__(1024) unsigned char sAhi[TPX * 128];  // 16 KB
    __shared__ __align__(1024) unsigned char sAlo[TPX * 128];  // 16 KB
    __shared__ __align__(1024) unsigned char sBhi[64 * 128];   // 8 KB
    __shared__ __align__(1024) unsigned char sBlo[64 * 128];   // 8 KB (48 KB)

    const int tid  = threadIdx.x;
    const int warp = tid >> 5;
    const int lane = tid & 31;

    // --- Stage B = W^T split ONCE per CTA ---
    for (int i = tid; i < 64 * 64; i += 128) {
        int n = i & 63;
        int k = i >> 6;
        float w = Wm[k * 64 + n];
        __nv_bfloat16 h = __float2bfloat16(w);
        __nv_bfloat16 l = __float2bfloat16(w - __bfloat162float(h));
        uint32_t off = SWZ((uint32_t)(n * 128 + k * 2));
        *reinterpret_cast<unsigned short*>(sBhi + off) = __bfloat16_as_ushort(h);
        *reinterpret_cast<unsigned short*>(sBlo + off) = __bfloat16_as_ushort(l);
    }

    // --- Loop-invariant addressing ---
    const int g = lane >> 2, t = lane & 3;
    const int px = warp * 32;
    const uint32_t mask   = (uint32_t)(lane & 7) << 4;
    const uint32_t aRow   = (uint32_t)(px + (lane & 15)) * 128;
    const uint32_t aChunk = (uint32_t)(lane & 16);
    const uint32_t bRow   = (uint32_t)((lane & 7) + ((lane & 16) >> 1)) * 128;
    const uint32_t bChunk = (uint32_t)((lane & 8) << 1);
    const uint32_t aHi = smem_u32(sAhi);
    const uint32_t aLo = smem_u32(sAlo);
    const uint32_t bHiA = smem_u32(sBhi);
    const uint32_t bLoA = smem_u32(sBlo);

    float bias0[8], bias1[8];
    #pragma unroll
    for (int n = 0; n < 8; n++) {
        bias0[n] = __ldg(&bm[n * 8 + 2 * t]);
        bias1[n] = __ldg(&bm[n * 8 + 2 * t + 1]);
    }

    // --- Persistent tile loop ---
    for (int tile = blockIdx.x; tile < NTILES; tile += NCTAS) {
        const int b   = tile / (HWSZ / TPX);
        const int hw0 = (tile - b * (HWSZ / TPX)) * TPX;

        // Stage A: thread = pixel; 64 batched strided LDGs, convert, STS.128
        {
            const float* fbase = feat + (size_t)b * CC * HWSZ + hw0 + tid;
            const uint32_t arow = (uint32_t)tid * 128;
            #pragma unroll
            for (int c = 0; c < 8; c++) {
                uint32_t hp[4], lp[4];
                #pragma unroll
                for (int j = 0; j < 4; j++) {
                    int k0 = c * 8 + 2 * j;
                    float a0 = fbase[(size_t)k0 * HWSZ];
                    float a1 = fbase[(size_t)(k0 + 1) * HWSZ];
                    __nv_bfloat16 h0 = __float2bfloat16(a0);
                    __nv_bfloat16 h1 = __float2bfloat16(a1);
                    __nv_bfloat16 l0 = __float2bfloat16(a0 - __bfloat162float(h0));
                    __nv_bfloat16 l1 = __float2bfloat16(a1 - __bfloat162float(h1));
                    hp[j] = (uint32_t)__bfloat16_as_ushort(h0) |
                            ((uint32_t)__bfloat16_as_ushort(h1) << 16);
                    lp[j] = (uint32_t)__bfloat16_as_ushort(l0) |
                            ((uint32_t)__bfloat16_as_ushort(l1) << 16);
                }
                uint32_t off = SWZ(arow + c * 16);
                asm volatile("st.shared.v4.b32 [%0], {%1, %2, %3, %4};"
                             :: "r"(aHi + off),
                                "r"(hp[0]), "r"(hp[1]), "r"(hp[2]), "r"(hp[3]) : "memory");
                asm volatile("st.shared.v4.b32 [%0], {%1, %2, %3, %4};"
                             :: "r"(aLo + off),
                                "r"(lp[0]), "r"(lp[1]), "r"(lp[2]), "r"(lp[3]) : "memory");
            }
        }

        // Prefetch tile i+1 into L2 (register-free; drains behind MMA)
        {
            const int nxt = tile + NCTAS;
            if (nxt < NTILES) {
                const int bn  = nxt / (HWSZ / TPX);
                const int hwn = (nxt - bn * (HWSZ / TPX)) * TPX;
                const float* fn = feat + (size_t)bn * CC * HWSZ + hwn + tid;
                #pragma unroll
                for (int k = 0; k < 64; k++)
                    PREFETCH_L2(fn + (size_t)k * HWSZ);
            }
        }
        __syncthreads();

        // MMA: k-outer; each k's fragments loaded once; bHi reused twice
        float c_[2][8][4];
        #pragma unroll
        for (int m = 0; m < 2; m++)
            #pragma unroll
            for (int n = 0; n < 8; n++)
                #pragma unroll
                for (int r = 0; r < 4; r++) c_[m][n][r] = 0.0f;

        #pragma unroll
        for (int k = 0; k < 4; k++) {
            const uint32_t ac = (aChunk + (uint32_t)k * 32) ^ mask;  // no carry
            const uint32_t bc = (bChunk + (uint32_t)k * 32) ^ mask;
            uint32_t ah0[4], ah1[4], al0[4], al1[4];
            LDSM4(ah0, aHi + aRow + ac);
            LDSM4(ah1, aHi + aRow + 2048 + ac);
            LDSM4(al0, aLo + aRow + ac);
            LDSM4(al1, aLo + aRow + 2048 + ac);
            uint32_t bh[8][2], bl[8][2];
            #pragma unroll
            for (int np = 0; np < 4; np++) {
                uint32_t r4[4];
                LDSM4(r4, bHiA + bRow + (uint32_t)np * 2048 + bc);
                bh[2 * np][0] = r4[0]; bh[2 * np][1] = r4[1];
                bh[2 * np + 1][0] = r4[2]; bh[2 * np + 1][1] = r4[3];
                LDSM4(r4, bLoA + bRow + (uint32_t)np * 2048 + bc);
                bl[2 * np][0] = r4[0]; bl[2 * np][1] = r4[1];
                bl[2 * np + 1][0] = r4[2]; bl[2 * np + 1][1] = r4[3];
            }
            #pragma unroll
            for (int n = 0; n < 8; n++) {
                MMA16816(c_[0][n], ah0, bh[n][0], bh[n][1]);   // hi*hi
                MMA16816(c_[1][n], ah1, bh[n][0], bh[n][1]);
                MMA16816(c_[0][n], ah0, bl[n][0], bl[n][1]);   // hi*lo
                MMA16816(c_[1][n], ah1, bl[n][0], bl[n][1]);
                MMA16816(c_[0][n], al0, bh[n][0], bh[n][1]);   // lo*hi
                MMA16816(c_[1][n], al1, bh[n][0], bh[n][1]);
            }
        }

        // Epilogue: mask + bias; per-channel stores are full 32B sectors
        const unsigned char* occp = g_occ + b * HWSZ + hw0 + px + g;
        float msk[4];
        msk[0] = occp[0]  ? 1.0f : 0.0f;
        msk[1] = occp[8]  ? 1.0f : 0.0f;
        msk[2] = occp[16] ? 1.0f : 0.0f;
        msk[3] = occp[24] ? 1.0f : 0.0f;

        float* ob = out + (size_t)b * CC * HWSZ;
        #pragma unroll
        for (int m = 0; m < 2; m++) {
            const int hwA = hw0 + px + m * 16 + g;
            const int hwB = hwA + 8;
            const float mA = msk[2 * m], mB = msk[2 * m + 1];
            #pragma unroll
            for (int n = 0; n < 8; n++) {
                const size_t ch = (size_t)(n * 8 + 2 * t);
                ob[ch * HWSZ + hwA]       = (c_[m][n][0] + bias0[n]) * mA;
                ob[(ch + 1) * HWSZ + hwA] = (c_[m][n][1] + bias1[n]) * mA;
                ob[ch * HWSZ + hwB]       = (c_[m][n][2] + bias0[n]) * mB;
                ob[(ch + 1) * HWSZ + hwB] = (c_[m][n][3] + bias1[n]) * mB;
            }
        }
        __syncthreads();   // all warps done reading sA before next staging
    }
}

// ---------------------------------------------------------------------------
extern "C" void kernel_launch(void* const* d_in, const int* in_sizes, int n_in,
                              void* d_out, int out_size) {
    const float* feat = (const float*)d_in[0];      // [B, C, H, W] f32
    const void*  pidx = d_in[1];                    // [B, P, L] int32 or int64
    const float* Wm   = (const float*)d_in[2];      // [C, C] f32
    const float* bm   = (const float*)d_in[3];      // [C] f32
    float*       out  = (float*)d_out;              // [B, C, H, W] f32

    (void)in_sizes; (void)n_in; (void)out_size;

    zero_probe_kernel<<<(BB * HWSZ / 16 + 255) / 256, 256>>>((const int*)pidx);
    mark_occ_kernel<<<(NSTEPS + 255) / 256, 256>>>(pidx);

    mma_gemm_kernel<<<NCTAS, 128>>>(feat, Wm, bm, out);
}

// round 16
// speedup vs baseline: 1.3819x; 1.0282x over previous
#include <cuda_runtime.h>
#include <cuda_bf16.h>
#include <cstdint>

#define BB 16
#define CC 64
#define HH 192
#define WWID 192
#define HWSZ (HH * WWID)            // 36864
#define NSTEPS (BB * 128 * 512)     // 1,048,576 path steps
#define TPX 128                     // pixels per tile (MMA M)
#define NTILES (BB * (HWSZ / TPX))  // 4608
#define NCTAS (148 * 3)             // persistent grid

// Invariant: g_occ is all-zero at every kernel_launch entry.
// (CUDA zero-inits device globals; the GEMM epilogue re-zeroes every byte it
// reads — consumer cleanup — so each launch restores the invariant.)
__device__ unsigned char g_occ[BB * HWSZ];

// ---------------------------------------------------------------------------
// Mark occupancy. Self-probing: every block reads the SAME first 256 int32
// pairs (1 KB, L2-broadcast); int64 data (values < 36864) has all hi-words
// zero, int32 random data cannot have 256 consecutive zeros at odd positions.
// 1024 elements per block, 4 per thread, vectorized loads.
// ---------------------------------------------------------------------------
__global__ void __launch_bounds__(256)
mark_occ_kernel(const void* __restrict__ pidx) {
    const int tid = threadIdx.x;
    const int* words = (const int*)pidx;
    int nz = (words[2 * tid + 1] != 0) ? 1 : 0;
    const int anyNz = __syncthreads_or(nz);   // anyNz != 0  =>  int32 data

    const int base = blockIdx.x * 1024 + tid * 4;
    int hw[4];
    if (!anyNz) {
        const longlong2* p = (const longlong2*)pidx;
        longlong2 v0 = p[base >> 1];
        longlong2 v1 = p[(base >> 1) + 1];
        hw[0] = (int)v0.x; hw[1] = (int)v0.y;
        hw[2] = (int)v1.x; hw[3] = (int)v1.y;
    } else {
        int4 v = ((const int4*)pidx)[base >> 2];
        hw[0] = v.x; hw[1] = v.y; hw[2] = v.z; hw[3] = v.w;
    }
    #pragma unroll
    for (int e = 0; e < 4; e++) {
        int b = (base + e) >> 16;             // P*L = 65536 steps per batch
        if ((unsigned)hw[e] < (unsigned)HWSZ)
            g_occ[b * HWSZ + hw[e]] = 1;
    }
}

// ---------------------------------------------------------------------------
__device__ __forceinline__ uint32_t smem_u32(const void* p) {
    uint32_t a;
    asm("{ .reg .u64 t; cvta.to.shared.u64 t, %1; cvt.u32.u64 %0, t; }"
        : "=r"(a) : "l"(p));
    return a;
}
#define SWZ(o) ((uint32_t)(o) ^ ((((uint32_t)(o)) >> 3) & 0x70))

#define LDSM4(R, ADDR)                                                        \
    asm volatile("ldmatrix.sync.aligned.m8n8.x4.shared.b16 {%0,%1,%2,%3}, [%4];" \
                 : "=r"((R)[0]), "=r"((R)[1]), "=r"((R)[2]), "=r"((R)[3])     \
                 : "r"(ADDR))

#define MMA16816(C, A, B0, B1)                                                \
    asm volatile("mma.sync.aligned.m16n8k16.row.col.f32.bf16.bf16.f32 "       \
                 "{%0,%1,%2,%3}, {%4,%5,%6,%7}, {%8,%9}, {%0,%1,%2,%3};"      \
                 : "+f"((C)[0]), "+f"((C)[1]), "+f"((C)[2]), "+f"((C)[3])     \
                 : "r"((A)[0]), "r"((A)[1]), "r"((A)[2]), "r"((A)[3]),        \
                   "r"(B0), "r"(B1))

#define PREFETCH_L2(ADDR)                                                     \
    asm volatile("prefetch.global.L2 [%0];" :: "l"(ADDR))

// ---------------------------------------------------------------------------
// Persistent masked GEMM (R15 champion). ONLY change: epilogue zeroes the occ
// bytes it just consumed (each byte owned by exactly one warp of one tile),
// restoring the all-zero invariant for the next launch/replay.
// ---------------------------------------------------------------------------
__global__ void __launch_bounds__(128, 3)
mma_gemm_kernel(const float* __restrict__ feat,
                const float* __restrict__ Wm,     // [64][64] (k, c)
                const float* __restrict__ bm,     // [64]
                float* __restrict__ out) {
    __shared__ __align__(1024) unsigned char sAhi[TPX * 128];  // 16 KB
    __shared__ __align__(1024) unsigned char sAlo[TPX * 128];  // 16 KB
    __shared__ __align__(1024) unsigned char sBhi[64 * 128];   // 8 KB
    __shared__ __align__(1024) unsigned char sBlo[64 * 128];   // 8 KB (48 KB)

    const int tid  = threadIdx.x;
    const int warp = tid >> 5;
    const int lane = tid & 31;

    // --- Stage B = W^T split ONCE per CTA ---
    for (int i = tid; i < 64 * 64; i += 128) {
        int n = i & 63;
        int k = i >> 6;
        float w = Wm[k * 64 + n];
        __nv_bfloat16 h = __float2bfloat16(w);
        __nv_bfloat16 l = __float2bfloat16(w - __bfloat162float(h));
        uint32_t off = SWZ((uint32_t)(n * 128 + k * 2));
        *reinterpret_cast<unsigned short*>(sBhi + off) = __bfloat16_as_ushort(h);
        *reinterpret_cast<unsigned short*>(sBlo + off) = __bfloat16_as_ushort(l);
    }

    // --- Loop-invariant addressing ---
    const int g = lane >> 2, t = lane & 3;
    const int px = warp * 32;
    const uint32_t mask   = (uint32_t)(lane & 7) << 4;
    const uint32_t aRow   = (uint32_t)(px + (lane & 15)) * 128;
    const uint32_t aChunk = (uint32_t)(lane & 16);
    const uint32_t bRow   = (uint32_t)((lane & 7) + ((lane & 16) >> 1)) * 128;
    const uint32_t bChunk = (uint32_t)((lane & 8) << 1);
    const uint32_t aHi = smem_u32(sAhi);
    const uint32_t aLo = smem_u32(sAlo);
    const uint32_t bHiA = smem_u32(sBhi);
    const uint32_t bLoA = smem_u32(sBlo);

    float bias0[8], bias1[8];
    #pragma unroll
    for (int n = 0; n < 8; n++) {
        bias0[n] = __ldg(&bm[n * 8 + 2 * t]);
        bias1[n] = __ldg(&bm[n * 8 + 2 * t + 1]);
    }

    // --- Persistent tile loop ---
    for (int tile = blockIdx.x; tile < NTILES; tile += NCTAS) {
        const int b   = tile / (HWSZ / TPX);
        const int hw0 = (tile - b * (HWSZ / TPX)) * TPX;

        // Stage A: thread = pixel; 64 batched strided LDGs, convert, STS.128
        {
            const float* fbase = feat + (size_t)b * CC * HWSZ + hw0 + tid;
            const uint32_t arow = (uint32_t)tid * 128;
            #pragma unroll
            for (int c = 0; c < 8; c++) {
                uint32_t hp[4], lp[4];
                #pragma unroll
                for (int j = 0; j < 4; j++) {
                    int k0 = c * 8 + 2 * j;
                    float a0 = fbase[(size_t)k0 * HWSZ];
                    float a1 = fbase[(size_t)(k0 + 1) * HWSZ];
                    __nv_bfloat16 h0 = __float2bfloat16(a0);
                    __nv_bfloat16 h1 = __float2bfloat16(a1);
                    __nv_bfloat16 l0 = __float2bfloat16(a0 - __bfloat162float(h0));
                    __nv_bfloat16 l1 = __float2bfloat16(a1 - __bfloat162float(h1));
                    hp[j] = (uint32_t)__bfloat16_as_ushort(h0) |
                            ((uint32_t)__bfloat16_as_ushort(h1) << 16);
                    lp[j] = (uint32_t)__bfloat16_as_ushort(l0) |
                            ((uint32_t)__bfloat16_as_ushort(l1) << 16);
                }
                uint32_t off = SWZ(arow + c * 16);
                asm volatile("st.shared.v4.b32 [%0], {%1, %2, %3, %4};"
                             :: "r"(aHi + off),
                                "r"(hp[0]), "r"(hp[1]), "r"(hp[2]), "r"(hp[3]) : "memory");
                asm volatile("st.shared.v4.b32 [%0], {%1, %2, %3, %4};"
                             :: "r"(aLo + off),
                                "r"(lp[0]), "r"(lp[1]), "r"(lp[2]), "r"(lp[3]) : "memory");
            }
        }

        // Prefetch tile i+1 into L2 (register-free; drains behind MMA)
        {
            const int nxt = tile + NCTAS;
            if (nxt < NTILES) {
                const int bn  = nxt / (HWSZ / TPX);
                const int hwn = (nxt - bn * (HWSZ / TPX)) * TPX;
                const float* fn = feat + (size_t)bn * CC * HWSZ + hwn + tid;
                #pragma unroll
                for (int k = 0; k < 64; k++)
                    PREFETCH_L2(fn + (size_t)k * HWSZ);
            }
        }
        __syncthreads();

        // MMA: k-outer; each k's fragments loaded once; bHi reused twice
        float c_[2][8][4];
        #pragma unroll
        for (int m = 0; m < 2; m++)
            #pragma unroll
            for (int n = 0; n < 8; n++)
                #pragma unroll
                for (int r = 0; r < 4; r++) c_[m][n][r] = 0.0f;

        #pragma unroll
        for (int k = 0; k < 4; k++) {
            const uint32_t ac = (aChunk + (uint32_t)k * 32) ^ mask;  // no carry
            const uint32_t bc = (bChunk + (uint32_t)k * 32) ^ mask;
            uint32_t ah0[4], ah1[4], al0[4], al1[4];
            LDSM4(ah0, aHi + aRow + ac);
            LDSM4(ah1, aHi + aRow + 2048 + ac);
            LDSM4(al0, aLo + aRow + ac);
            LDSM4(al1, aLo + aRow + 2048 + ac);
            uint32_t bh[8][2], bl[8][2];
            #pragma unroll
            for (int np = 0; np < 4; np++) {
                uint32_t r4[4];
                LDSM4(r4, bHiA + bRow + (uint32_t)np * 2048 + bc);
                bh[2 * np][0] = r4[0]; bh[2 * np][1] = r4[1];
                bh[2 * np + 1][0] = r4[2]; bh[2 * np + 1][1] = r4[3];
                LDSM4(r4, bLoA + bRow + (uint32_t)np * 2048 + bc);
                bl[2 * np][0] = r4[0]; bl[2 * np][1] = r4[1];
                bl[2 * np + 1][0] = r4[2]; bl[2 * np + 1][1] = r4[3];
            }
            #pragma unroll
            for (int n = 0; n < 8; n++) {
                MMA16816(c_[0][n], ah0, bh[n][0], bh[n][1]);   // hi*hi
                MMA16816(c_[1][n], ah1, bh[n][0], bh[n][1]);
                MMA16816(c_[0][n], ah0, bl[n][0], bl[n][1]);   // hi*lo
                MMA16816(c_[1][n], ah1, bl[n][0], bl[n][1]);
                MMA16816(c_[0][n], al0, bh[n][0], bh[n][1]);   // lo*hi
                MMA16816(c_[1][n], al1, bh[n][0], bh[n][1]);
            }
        }

        // Epilogue: mask + bias; per-channel stores are full 32B sectors
        unsigned char* occp = g_occ + b * HWSZ + hw0 + px + g;
        float msk[4];
        msk[0] = occp[0]  ? 1.0f : 0.0f;
        msk[1] = occp[8]  ? 1.0f : 0.0f;
        msk[2] = occp[16] ? 1.0f : 0.0f;
        msk[3] = occp[24] ? 1.0f : 0.0f;

        float* ob = out + (size_t)b * CC * HWSZ;
        #pragma unroll
        for (int m = 0; m < 2; m++) {
            const int hwA = hw0 + px + m * 16 + g;
            const int hwB = hwA + 8;
            const float mA = msk[2 * m], mB = msk[2 * m + 1];
            #pragma unroll
            for (int n = 0; n < 8; n++) {
                const size_t ch = (size_t)(n * 8 + 2 * t);
                ob[ch * HWSZ + hwA]       = (c_[m][n][0] + bias0[n]) * mA;
                ob[(ch + 1) * HWSZ + hwA] = (c_[m][n][1] + bias1[n]) * mA;
                ob[ch * HWSZ + hwB]       = (c_[m][n][2] + bias0[n]) * mB;
                ob[(ch + 1) * HWSZ + hwB] = (c_[m][n][3] + bias1[n]) * mB;
            }
        }

        // Consumer cleanup: restore occ==0 for the next launch/replay.
        // Safe: the masked STGs above data-depend on the occ loads, so every
        // lane's load has completed before this store instruction can issue;
        // each byte belongs to exactly one warp of exactly one tile.
        if (t == 0) {
            occp[0] = 0; occp[8] = 0; occp[16] = 0; occp[24] = 0;
        }
        __syncthreads();   // all warps done reading sA before next staging
    }
}

// ---------------------------------------------------------------------------
extern "C" void kernel_launch(void* const* d_in, const int* in_sizes, int n_in,
                              void* d_out, int out_size) {
    const float* feat = (const float*)d_in[0];      // [B, C, H, W] f32
    const void*  pidx = d_in[1];                    // [B, P, L] int32 or int64
    const float* Wm   = (const float*)d_in[2];      // [C, C] f32
    const float* bm   = (const float*)d_in[3];      // [C] f32
    float*       out  = (float*)d_out;              // [B, C, H, W] f32

    (void)in_sizes; (void)n_in; (void)out_size;

    mark_occ_kernel<<<NSTEPS / 1024, 256>>>(pidx);
    mma_gemm_kernel<<<NCTAS, 128>>>(feat, Wm, bm, out);
}